// round 11
// baseline (speedup 1.0000x reference)
#include <cuda_runtime.h>
#include <cuda_fp16.h>
#include <cstdint>

// Problem constants: B=16, C=128, N=M=2048
#define B_  16
#define C_  128
#define N_  2048
#define K2F  14.4269504089f    // 10 * log2(e)
#define LN2F 0.69314718055995f

#define NTILE   256            // n rows per CTA; 16 per warp
#define MCHUNK  32
#define NCHUNKS 64
#define THREADS 512
#define NCTAS   128            // grid 8 x 16

// SMEM u32 layout. B double-buffers (fragment-major) alias the A-stage.
#define APAD   264             // A-stage: [64 kpair][APAD]
#define ASTAGE (64 * APAD)     // 16896 u32
#define BBUF   2048            // per buffer: 8 ks x [2 b01][32 lane][4 grp] u32
#define POSU   ASTAGE          // red2/posv: 512 floats
#define FLGU   (POSU + 512)
#define SMEMU  (FLGU + 4)

__device__ float g_partial[NCTAS];
__device__ unsigned int g_count;

__device__ __forceinline__ float ex2f(float x) {
    float y;
    asm("ex2.approx.ftz.f32 %0, %1;" : "=f"(y) : "f"(x));
    return y;
}
__device__ __forceinline__ float lg2f(float x) {
    float y;
    asm("lg2.approx.ftz.f32 %0, %1;" : "=f"(y) : "f"(x));
    return y;
}
__device__ __forceinline__ void mma_f16(float* c, const uint32_t* a,
                                        uint32_t b0, uint32_t b1) {
    asm volatile("mma.sync.aligned.m16n8k16.row.col.f32.f16.f16.f32 "
                 "{%0,%1,%2,%3}, {%4,%5,%6,%7}, {%8,%9}, {%0,%1,%2,%3};"
                 : "+f"(c[0]), "+f"(c[1]), "+f"(c[2]), "+f"(c[3])
                 : "r"(a[0]), "r"(a[1]), "r"(a[2]), "r"(a[3]), "r"(b0), "r"(b1));
}

extern __shared__ __align__(16) uint32_t smu[];

__global__ void __launch_bounds__(THREADS, 1)
patchnce_main(const float* __restrict__ q,
              const float* __restrict__ p,
              const float* __restrict__ neg,
              float* __restrict__ out) {
    const int tid  = threadIdx.x;
    const int w    = tid >> 5;          // 16 warps; rows w*16..w*16+15
    const int lane = tid & 31;
    const int g    = lane >> 2;
    const int t4   = lane & 3;
    const int b    = blockIdx.y;
    const int n0   = blockIdx.x * NTILE;

    float* red2 = (float*)&smu[POSU];   // 512; folds to posv[256]
    int*   flag = (int*)&smu[FLGU];

    // ------ Phase 1: stage Q tile as f16x2 kpairs + positive dot -----------
    {
        const int row = tid & 255;
        const int kh  = tid >> 8;                   // k-half (2x32 kpairs)
        const float* qb = q + (size_t)b * C_ * N_ + n0 + row;
        const float* pb = p + (size_t)b * C_ * N_ + n0 + row;
        float pd = 0.f;
#pragma unroll 8
        for (int kp = kh * 32; kp < kh * 32 + 32; kp++) {
            float q0 = qb[(size_t)(2 * kp)     * N_];
            float q1 = qb[(size_t)(2 * kp + 1) * N_];
            float p0 = pb[(size_t)(2 * kp)     * N_];
            float p1 = pb[(size_t)(2 * kp + 1) * N_];
            pd = fmaf(q0, p0, fmaf(q1, p1, pd));
            __half2 h = __floats2half2_rn(q0, q1);
            smu[kp * APAD + row] = *(uint32_t*)&h;
        }
        red2[tid] = pd;
    }
    __syncthreads();
    if (tid < 256) red2[tid] += red2[tid + 256];    // posv = red2[0..255]

    // ------ Phase 2: A fragments (1 m16 block x 8 ksteps) -> 32 registers --
    uint32_t afr[32];
    {
        const int rb = w * 16 + g;
#pragma unroll
        for (int ks = 0; ks < 8; ks++) {
            uint32_t* a = afr + ks * 4;
            a[0] = smu[(ks * 8 + t4)     * APAD + rb];
            a[1] = smu[(ks * 8 + t4)     * APAD + rb + 8];
            a[2] = smu[(ks * 8 + t4 + 4) * APAD + rb];
            a[3] = smu[(ks * 8 + t4 + 4) * APAD + rb + 8];
        }
    }
    __syncthreads();   // afr + posv fold done; A-stage becomes B buffers

    // ------ Phase 3: pipelined streaming, fragment-major B -----------------
    const float* nb = neg + (size_t)b * C_ * N_;
    const int kp  = tid >> 3;          // 0..63: producer kpair
    const int mq  = tid & 7;           // producer m-quad

    // producer scatter coords (fragment-major destination)
    const int pks  = kp >> 3;
    const int pr8  = kp & 7;
    const uint32_t pbase = (uint32_t)(pks * 256 + (pr8 >> 2) * 128 + (pr8 & 3) * 4);

    float4 pr0, pr1;
    auto loadB = [&](int ch) {
        const float* s = nb + ch * MCHUNK + mq * 4;
        pr0 = *(const float4*)(s + (size_t)(2 * kp)     * N_);
        pr1 = *(const float4*)(s + (size_t)(2 * kp + 1) * N_);
    };
    auto storeB = [&](int buf) {
        uint32_t* bb = smu + buf * BBUF;
        __half2 h0 = __floats2half2_rn(pr0.x, pr1.x);
        __half2 h1 = __floats2half2_rn(pr0.y, pr1.y);
        __half2 h2 = __floats2half2_rn(pr0.z, pr1.z);
        __half2 h3 = __floats2half2_rn(pr0.w, pr1.w);
        const int c0 = mq * 4;
        bb[pbase + ((c0 + 0) & 7) * 16 + ((c0 + 0) >> 3)] = *(uint32_t*)&h0;
        bb[pbase + ((c0 + 1) & 7) * 16 + ((c0 + 1) >> 3)] = *(uint32_t*)&h1;
        bb[pbase + ((c0 + 2) & 7) * 16 + ((c0 + 2) >> 3)] = *(uint32_t*)&h2;
        bb[pbase + ((c0 + 3) & 7) * 16 + ((c0 + 3) >> 3)] = *(uint32_t*)&h3;
    };

    float rmax2[2], rsum[2];
#pragma unroll
    for (int s = 0; s < 2; s++) { rmax2[s] = -1e30f; rsum[s] = 0.f; }

    float acc0[4][4], acc1[4][4];

    auto softmax_slot = [&](float (&acc)[4][4], int h) {
        float v0 = acc[0][h*2], v1 = acc[0][h*2+1];
        float v2 = acc[1][h*2], v3 = acc[1][h*2+1];
        float v4 = acc[2][h*2], v5 = acc[2][h*2+1];
        float v6 = acc[3][h*2], v7 = acc[3][h*2+1];
        float vm = fmaxf(fmaxf(fmaxf(v0, v1), fmaxf(v2, v3)),
                         fmaxf(fmaxf(v4, v5), fmaxf(v6, v7)));
        float nm = fmaxf(rmax2[h], vm * K2F);
        rsum[h] *= ex2f(rmax2[h] - nm);
        rmax2[h] = nm;
        const float r = nm;
        __half2 e01 = h2exp2(__floats2half2_rn(fmaf(v0, K2F, -r), fmaf(v1, K2F, -r)));
        __half2 e23 = h2exp2(__floats2half2_rn(fmaf(v2, K2F, -r), fmaf(v3, K2F, -r)));
        __half2 e45 = h2exp2(__floats2half2_rn(fmaf(v4, K2F, -r), fmaf(v5, K2F, -r)));
        __half2 e67 = h2exp2(__floats2half2_rn(fmaf(v6, K2F, -r), fmaf(v7, K2F, -r)));
        __half2 st = __hadd2(__hadd2(e01, e23), __hadd2(e45, e67));
        float2 f = __half22float2(st);
        rsum[h] += f.x + f.y;
    };

    // fused MMA over fragment-major buffer: 2 LDS.128 per ks (conflict-free)
    auto fused = [&](int buf, float (&aN)[4][4], float (&aO)[4][4], bool doSoft) {
        const uint32_t* bb = smu + buf * BBUF;
#pragma unroll
        for (int i = 0; i < 4; i++)
#pragma unroll
            for (int j = 0; j < 4; j++) aN[i][j] = 0.f;

        uint4 c0 = *(const uint4*)&bb[lane * 4];
        uint4 c1 = *(const uint4*)&bb[128 + lane * 4];
#pragma unroll
        for (int ks = 0; ks < 8; ks++) {
            uint4 n0 = c0, n1 = c1;
            if (ks < 7) {
                n0 = *(const uint4*)&bb[(ks + 1) * 256 + lane * 4];
                n1 = *(const uint4*)&bb[(ks + 1) * 256 + 128 + lane * 4];
            }
            mma_f16(aN[0], afr + ks * 4, c0.x, c1.x);
            mma_f16(aN[1], afr + ks * 4, c0.y, c1.y);
            if (doSoft && ks == 2) softmax_slot(aO, 0);
            mma_f16(aN[2], afr + ks * 4, c0.z, c1.z);
            mma_f16(aN[3], afr + ks * 4, c0.w, c1.w);
            if (doSoft && ks == 5) softmax_slot(aO, 1);
            c0 = n0; c1 = n1;
        }
    };
    auto softmax_full = [&](float (&acc)[4][4]) {
        softmax_slot(acc, 0);
        softmax_slot(acc, 1);
    };

    // Prologue
    loadB(0); storeB(0); loadB(1);
    __syncthreads();
    fused(0, acc0, acc1, false);          // chunk 0 -> acc0

    // Steady state: fused(c+1) interleaves softmax(c)
#pragma unroll 1
    for (int ch = 0; ch < NCHUNKS; ch += 2) {
        if (ch + 1 < NCHUNKS) {
            storeB(1);
            if (ch + 2 < NCHUNKS) loadB(ch + 2);
            __syncthreads();
            fused(1, acc1, acc0, true);
        } else {
            softmax_full(acc0);
        }
        if (ch + 2 < NCHUNKS) {
            storeB(0);
            if (ch + 3 < NCHUNKS) loadB(ch + 3);
            __syncthreads();
            fused(0, acc0, acc1, true);
        } else if (ch + 1 < NCHUNKS) {
            softmax_full(acc1);
        }
    }

    // ------ Combine the 4 lanes (t4) sharing each row ----------------------
#pragma unroll
    for (int s = 0; s < 2; s++) {
#pragma unroll
        for (int d = 1; d <= 2; d <<= 1) {
            float om = __shfl_xor_sync(0xFFFFFFFFu, rmax2[s], d);
            float os = __shfl_xor_sync(0xFFFFFFFFu, rsum[s], d);
            float nm = fmaxf(rmax2[s], om);
            rsum[s] = rsum[s] * ex2f(rmax2[s] - nm) + os * ex2f(om - nm);
            rmax2[s] = nm;
        }
    }

    float loss = 0.f;
    if (t4 == 0) {
#pragma unroll
        for (int h = 0; h < 2; h++) {
            const int r = w * 16 + h * 8 + g;
            float lp2 = red2[r] * K2F;
            float M2 = fmaxf(rmax2[h], lp2);
            float S2 = rsum[h] * ex2f(rmax2[h] - M2) + ex2f(lp2 - M2);
            loss += (M2 + lg2f(S2) - lp2) * LN2F;
        }
    }

    // ------ Deterministic per-CTA reduction (reuse B-buffer smem) ----------
    __syncthreads();
    float* tmp = (float*)smu;
    tmp[tid] = loss;
    __syncthreads();
    for (int o = 256; o > 0; o >>= 1) {
        if (tid < o) tmp[tid] += tmp[tid + o];
        __syncthreads();
    }

    // ------ Cross-CTA fold: last CTA finishes ------------------------------
    const int cta = blockIdx.y * 8 + blockIdx.x;
    if (tid == 0) {
        g_partial[cta] = tmp[0];
        __threadfence();
        unsigned v = atomicAdd(&g_count, 1u);
        *flag = (v == NCTAS - 1) ? 1 : 0;
    }
    __syncthreads();
    if (*flag) {
        __threadfence();
        tmp[tid] = (tid < NCTAS) ? g_partial[tid] : 0.f;
        __syncthreads();
        for (int o = 64; o > 0; o >>= 1) {
            if (tid < o) tmp[tid] += tmp[tid + o];
            __syncthreads();
        }
        if (tid == 0) {
            out[0] = tmp[0] / (float)(B_ * N_);
            g_count = 0;
        }
    }
}

// ---------------------------------------------------------------------------
extern "C" void kernel_launch(void* const* d_in, const int* in_sizes, int n_in,
                              void* d_out, int out_size) {
    const float* q   = (const float*)d_in[0];
    const float* pos = (const float*)d_in[1];
    const float* neg = (const float*)d_in[2];
    float* out = (float*)d_out;

    cudaFuncSetAttribute(patchnce_main,
                         cudaFuncAttributeMaxDynamicSharedMemorySize,
                         SMEMU * sizeof(uint32_t));
    patchnce_main<<<dim3(8, 16), THREADS, SMEMU * sizeof(uint32_t)>>>(q, pos, neg, out);
}